// round 9
// baseline (speedup 1.0000x reference)
#include <cuda_runtime.h>

#define NN 100000
#define NE 1200000
#define NG 512
#define D  64
#define NC 10
#define RP2 68           // padded smem row: 16B-aligned, conflict-free rg spacing
#define NB 391           // scan blocks = ceil(NN/256)

// ---------------- scratch (device globals; no allocation) ----------------
__device__ int   g_degi[NN];
__device__ float g_dinv[NN];
__device__ float g_y[NN * D];     // scaled linear output  dinv[n] * (X W)[n]
__device__ float g_h[NN * D];     // layer-1 activations
__device__ float g_pool1[NG * D];
__device__ float g_pool2[NG * D];
__device__ int   g_cnti[NG];
// CSR
__device__ int   g_scan[NN];
__device__ int   g_bsum[NB];
__device__ int   g_boff[NB];
__device__ int   g_start[NN + 1];
__device__ int   g_pos[NN];
__device__ int   g_ecol[NE];

__device__ __forceinline__ void red_v4(float4* dst, float4 v) {
    asm volatile("red.global.add.v4.f32 [%0], {%1,%2,%3,%4};"
                 :: "l"(dst), "f"(v.x), "f"(v.y), "f"(v.z), "f"(v.w) : "memory");
}

// ---------------- setup kernels ----------------

__global__ void k_init() {
    int i = blockIdx.x * blockDim.x + threadIdx.x;
    if (i < NN) g_degi[i] = 0;
    if (i < NG * D) { g_pool1[i] = 0.0f; g_pool2[i] = 0.0f; }
    if (i < NG) g_cnti[i] = 0;
}

__global__ void k_deg(const int* __restrict__ rows) {
    int e = blockIdx.x * blockDim.x + threadIdx.x;
    if (e >= NE) return;
    unsigned r = (unsigned)rows[e];
    if (r < NN) atomicAdd(&g_degi[r], 1);
}

__global__ void k_prep(const int* __restrict__ batch) {
    int i = blockIdx.x * blockDim.x + threadIdx.x;
    if (i >= NN) return;
    g_dinv[i] = rsqrtf((float)g_degi[i] + 1.0f);   // +1 = self loop
    unsigned g = (unsigned)batch[i];
    if (g < NG) atomicAdd(&g_cnti[g], 1);
}

// per-block inclusive scan of degrees
__global__ void k_scanA() {
    __shared__ int s[256];
    int t = threadIdx.x;
    int i = blockIdx.x * 256 + t;
    int d = (i < NN) ? g_degi[i] : 0;
    s[t] = d;
    __syncthreads();
#pragma unroll
    for (int off = 1; off < 256; off <<= 1) {
        int v = (t >= off) ? s[t - off] : 0;
        __syncthreads();
        s[t] += v;
        __syncthreads();
    }
    if (i < NN) g_scan[i] = s[t];
    if (t == 255) g_bsum[blockIdx.x] = s[255];
}

// single-block exclusive scan of block sums
__global__ void k_scanB() {
    __shared__ int s[512];
    int t = threadIdx.x;  // 512
    s[t] = (t < NB) ? g_bsum[t] : 0;
    __syncthreads();
#pragma unroll
    for (int off = 1; off < 512; off <<= 1) {
        int v = (t >= off) ? s[t - off] : 0;
        __syncthreads();
        s[t] += v;
        __syncthreads();
    }
    if (t < NB) g_boff[t] = (t == 0) ? 0 : s[t - 1];
    if (t == 511) g_start[NN] = s[511];
}

__global__ void k_scanC() {
    int i = blockIdx.x * blockDim.x + threadIdx.x;
    if (i >= NN) return;
    int st = g_scan[i] - g_degi[i] + g_boff[i >> 8];
    g_start[i] = st;
    g_pos[i] = st;
}

__global__ void k_fill(const int* __restrict__ rows, const int* __restrict__ cols) {
    int e = blockIdx.x * blockDim.x + threadIdx.x;
    if (e >= NE) return;
    unsigned r = (unsigned)rows[e];
    if (r >= NN) return;
    int p = atomicAdd(&g_pos[r], 1);
    g_ecol[p] = cols[e];
}

// ---------------- GEMM: g_y = dinv * (X W) ----------------
// Block: 256 thr, tile 128 rows x 64 cols. Warp (w&3)=row strip of 32,
// (w>>2)=col strip of 32. Thread: 8 rows (stride-4 interleaved) x 4 cols.
// Per 4-k step: 8 x-LDS.128 + 4 W-LDS.128 -> 128 FFMA.
__device__ __forceinline__ void gemm_body(const float* __restrict__ X,
                                          const float* __restrict__ W,
                                          int n0) {
    __shared__ float sW[D * D];
    __shared__ float sX[128 * RP2];
    int t = threadIdx.x;
    for (int i = t; i < 1024; i += 256)
        ((float4*)sW)[i] = ((const float4*)W)[i];
    for (int i = t; i < 2048; i += 256) {
        int r = i >> 4, c4 = i & 15;
        float4 v = make_float4(0.f, 0.f, 0.f, 0.f);
        if (n0 + r < NN) v = ((const float4*)X)[(n0 + r) * 16 + c4];
        *(float4*)&sX[r * RP2 + c4 * 4] = v;
    }
    __syncthreads();

    int w = t >> 5, lane = t & 31;
    int wr = (w & 3) * 32;
    int wc = (w >> 2) * 32;
    int rg = lane >> 3;          // 0..3
    int cg = lane & 7;           // 0..7
    int c  = wc + cg * 4;

    float4 acc[8];
#pragma unroll
    for (int j = 0; j < 8; j++) acc[j] = make_float4(0.f, 0.f, 0.f, 0.f);

#pragma unroll 4
    for (int k4 = 0; k4 < 16; k4++) {
        float4 wv0 = *(const float4*)&sW[(k4 * 4 + 0) * D + c];
        float4 wv1 = *(const float4*)&sW[(k4 * 4 + 1) * D + c];
        float4 wv2 = *(const float4*)&sW[(k4 * 4 + 2) * D + c];
        float4 wv3 = *(const float4*)&sW[(k4 * 4 + 3) * D + c];
#pragma unroll
        for (int j = 0; j < 8; j++) {
            float4 xv = *(const float4*)&sX[(wr + rg + 4 * j) * RP2 + k4 * 4];
            acc[j].x += xv.x * wv0.x + xv.y * wv1.x + xv.z * wv2.x + xv.w * wv3.x;
            acc[j].y += xv.x * wv0.y + xv.y * wv1.y + xv.z * wv2.y + xv.w * wv3.y;
            acc[j].z += xv.x * wv0.z + xv.y * wv1.z + xv.z * wv2.z + xv.w * wv3.z;
            acc[j].w += xv.x * wv0.w + xv.y * wv1.w + xv.z * wv2.w + xv.w * wv3.w;
        }
    }

#pragma unroll
    for (int j = 0; j < 8; j++) {
        int n = n0 + wr + rg + 4 * j;
        if (n < NN) {
            float s = g_dinv[n];
            ((float4*)g_y)[n * 16 + (c >> 2)] =
                make_float4(s * acc[j].x, s * acc[j].y, s * acc[j].z, s * acc[j].w);
        }
    }
}

__global__ void __launch_bounds__(256) k_gemm1(const float* __restrict__ X,
                                               const float* __restrict__ W) {
    gemm_body(X, W, blockIdx.x * 128);
}
__global__ void __launch_bounds__(256) k_gemm2(const float* __restrict__ W) {
    gemm_body(g_h, W, blockIdx.x * 128);
}

// ---------------- fused gather + finalize ----------------
__device__ __forceinline__ void gather_body(const float* __restrict__ b,
                                            const int* __restrict__ batch,
                                            float* __restrict__ pool,
                                            int store_h) {
    int idx = blockIdx.x * blockDim.x + threadIdx.x;
    int n = idx >> 4;
    int q = idx & 15;
    if (n >= NN) return;
    const float4* y4 = (const float4*)g_y;
    float4 acc = y4[n * 16 + q];                 // self loop term
    int s = g_start[n], e = g_start[n + 1];
    for (int ei = s; ei < e; ei++) {
        unsigned c = (unsigned)g_ecol[ei];
        if (c < NN) {
            float4 v = y4[c * 16 + q];
            acc.x += v.x; acc.y += v.y; acc.z += v.z; acc.w += v.w;
        }
    }
    float sc = g_dinv[n];
    float4 bb = ((const float4*)b)[q];
    float4 h;
    h.x = fmaxf(sc * acc.x + bb.x, 0.0f);
    h.y = fmaxf(sc * acc.y + bb.y, 0.0f);
    h.z = fmaxf(sc * acc.z + bb.z, 0.0f);
    h.w = fmaxf(sc * acc.w + bb.w, 0.0f);
    if (store_h) ((float4*)g_h)[n * 16 + q] = h;
    unsigned g = (unsigned)batch[n];
    if (g < NG) red_v4(((float4*)pool) + g * 16 + q, h);
}

__global__ void k_gather1(const float* __restrict__ b, const int* __restrict__ batch) {
    gather_body(b, batch, g_pool1, 1);
}
__global__ void k_gather2(const float* __restrict__ b, const int* __restrict__ batch) {
    gather_body(b, batch, g_pool2, 0);
}

// ---------------- head ----------------
__global__ void k_head(const float* __restrict__ Wl, const float* __restrict__ bl,
                       float* __restrict__ out) {
    int g = blockIdx.x;
    int lane = threadIdx.x;  // 32
    float denom = fmaxf((float)g_cnti[g], 1.0f);
    float v0 = (g_pool1[g * D + lane] + g_pool2[g * D + lane]) / denom;
    float v1 = (g_pool1[g * D + 32 + lane] + g_pool2[g * D + 32 + lane]) / denom;
    float z = (lane < NC) ? bl[lane] : 0.0f;
#pragma unroll
    for (int d = 0; d < 32; d++) {
        float a0 = __shfl_sync(0xffffffffu, v0, d);
        float a1 = __shfl_sync(0xffffffffu, v1, d);
        if (lane < NC) z += a0 * Wl[d * NC + lane] + a1 * Wl[(d + 32) * NC + lane];
    }
    if (lane < NC) z = fmaxf(z, 0.0f);
    float zm = (lane < NC) ? z : -1e30f;
#pragma unroll
    for (int off = 16; off; off >>= 1)
        zm = fmaxf(zm, __shfl_xor_sync(0xffffffffu, zm, off));
    float e = (lane < NC) ? expf(z - zm) : 0.0f;
#pragma unroll
    for (int off = 16; off; off >>= 1)
        e += __shfl_xor_sync(0xffffffffu, e, off);
    if (lane < NC) out[g * NC + lane] = z - zm - logf(e);
}

// ---------------- launch ----------------

extern "C" void kernel_launch(void* const* d_in, const int* in_sizes, int n_in,
                              void* d_out, int out_size) {
    const float* x     = (const float*)d_in[0];
    const int*   eidx  = (const int*)d_in[1];    // int32 (JAX x64 disabled)
    const int*   batch = (const int*)d_in[2];
    const float* W1    = (const float*)d_in[3];
    const float* b1    = (const float*)d_in[4];
    const float* W2    = (const float*)d_in[5];
    const float* b2    = (const float*)d_in[6];
    const float* Wl    = (const float*)d_in[7];
    const float* bl    = (const float*)d_in[8];
    float* out = (float*)d_out;

    const int* rows = eidx;        // edge_index[0] = targets
    const int* cols = eidx + NE;   // edge_index[1] = sources

    const int GB = (NN + 127) / 128;   // 782 gemm blocks

    // degrees, dinv, per-graph counts
    k_init<<<(NN + 255) / 256, 256>>>();
    k_deg<<<(NE + 255) / 256, 256>>>(rows);
    k_prep<<<(NN + 255) / 256, 256>>>(batch);

    // CSR build (reused by both convs)
    k_scanA<<<NB, 256>>>();
    k_scanB<<<1, 512>>>();
    k_scanC<<<NB, 256>>>();
    k_fill<<<(NE + 255) / 256, 256>>>(rows, cols);

    // conv1
    k_gemm1<<<GB, 256>>>(x, W1);
    k_gather1<<<(NN * 16 + 255) / 256, 256>>>(b1, batch);

    // conv2
    k_gemm2<<<GB, 256>>>(W2);
    k_gather2<<<(NN * 16 + 255) / 256, 256>>>(b2, batch);

    // head
    k_head<<<NG, 32>>>(Wl, bl, out);
}

// round 10
// speedup vs baseline: 1.0723x; 1.0723x over previous
#include <cuda_runtime.h>
#include <cuda_bf16.h>

#define NN 100000
#define NE 1200000
#define NG 512
#define D  64
#define NC 10
#define RP2 68           // padded smem row: 16B-aligned, conflict-free rg spacing
#define NB 391           // scan blocks = ceil(NN/256)

// ---------------- scratch (device globals; no allocation) ----------------
__device__ int   g_degi[NN];
__device__ float g_dinv[NN];
__device__ __nv_bfloat162 g_ybf[NN * 32];   // y rows in bf16 (32 x bf162 = 64 vals)
__device__ float g_h[NN * D];               // layer-1 activations (fp32)
__device__ float g_pool1[NG * D];
__device__ float g_pool2[NG * D];
__device__ int   g_cnti[NG];
// CSR
__device__ int   g_scan[NN];
__device__ int   g_bsum[NB];
__device__ int   g_boff[NB];
__device__ int   g_start[NN + 1];
__device__ int   g_pos[NN];
__device__ int   g_ecol[NE];

__device__ __forceinline__ void red_v4(float4* dst, float4 v) {
    asm volatile("red.global.add.v4.f32 [%0], {%1,%2,%3,%4};"
                 :: "l"(dst), "f"(v.x), "f"(v.y), "f"(v.z), "f"(v.w) : "memory");
}

// ---------------- setup kernels ----------------

__global__ void k_init() {
    int i = blockIdx.x * blockDim.x + threadIdx.x;
    if (i < NN) g_degi[i] = 0;
    if (i < NG * D) { g_pool1[i] = 0.0f; g_pool2[i] = 0.0f; }
    if (i < NG) g_cnti[i] = 0;
}

__global__ void k_deg(const int* __restrict__ rows) {
    int e = blockIdx.x * blockDim.x + threadIdx.x;
    if (e >= NE) return;
    unsigned r = (unsigned)rows[e];
    if (r < NN) atomicAdd(&g_degi[r], 1);
}

// per-block inclusive scan of degrees; fused: dinv + per-graph counts
__global__ void k_scanA(const int* __restrict__ batch) {
    __shared__ int s[256];
    int t = threadIdx.x;
    int i = blockIdx.x * 256 + t;
    int d = (i < NN) ? g_degi[i] : 0;
    s[t] = d;
    if (i < NN) {
        g_dinv[i] = rsqrtf((float)d + 1.0f);   // +1 = self loop
        unsigned g = (unsigned)batch[i];
        if (g < NG) atomicAdd(&g_cnti[g], 1);
    }
    __syncthreads();
#pragma unroll
    for (int off = 1; off < 256; off <<= 1) {
        int v = (t >= off) ? s[t - off] : 0;
        __syncthreads();
        s[t] += v;
        __syncthreads();
    }
    if (i < NN) g_scan[i] = s[t];
    if (t == 255) g_bsum[blockIdx.x] = s[255];
}

// single-block exclusive scan of block sums
__global__ void k_scanB() {
    __shared__ int s[512];
    int t = threadIdx.x;  // 512
    s[t] = (t < NB) ? g_bsum[t] : 0;
    __syncthreads();
#pragma unroll
    for (int off = 1; off < 512; off <<= 1) {
        int v = (t >= off) ? s[t - off] : 0;
        __syncthreads();
        s[t] += v;
        __syncthreads();
    }
    if (t < NB) g_boff[t] = (t == 0) ? 0 : s[t - 1];
    if (t == 511) g_start[NN] = s[511];
}

__global__ void k_scanC() {
    int i = blockIdx.x * blockDim.x + threadIdx.x;
    if (i >= NN) return;
    int st = g_scan[i] - g_degi[i] + g_boff[i >> 8];
    g_start[i] = st;
    g_pos[i] = st;
}

__global__ void k_fill(const int* __restrict__ rows, const int* __restrict__ cols) {
    int e = blockIdx.x * blockDim.x + threadIdx.x;
    if (e >= NE) return;
    unsigned r = (unsigned)rows[e];
    if (r >= NN) return;
    int p = atomicAdd(&g_pos[r], 1);
    g_ecol[p] = cols[e];
}

// ---------------- GEMM: y = dinv*(X W) -> bf16 ----------------
// Block 256 thr, tile 128 rows x 64 cols. Warp (w&3)=row strip, (w>>2)=col strip.
// Thread: 8 rows (stride-4 interleave) x 4 cols. 4 k per step, all-LDS.128.
__device__ __forceinline__ void gemm_body(const float* __restrict__ X,
                                          const float* __restrict__ W,
                                          int n0) {
    __shared__ float sW[D * D];
    __shared__ float sX[128 * RP2];
    int t = threadIdx.x;
    for (int i = t; i < 1024; i += 256)
        ((float4*)sW)[i] = ((const float4*)W)[i];
    for (int i = t; i < 2048; i += 256) {
        int r = i >> 4, c4 = i & 15;
        float4 v = make_float4(0.f, 0.f, 0.f, 0.f);
        if (n0 + r < NN) v = ((const float4*)X)[(n0 + r) * 16 + c4];
        *(float4*)&sX[r * RP2 + c4 * 4] = v;
    }
    __syncthreads();

    int w = t >> 5, lane = t & 31;
    int wr = (w & 3) * 32;
    int wc = (w >> 2) * 32;
    int rg = lane >> 3;          // 0..3
    int cg = lane & 7;           // 0..7
    int c  = wc + cg * 4;

    float4 acc[8];
#pragma unroll
    for (int j = 0; j < 8; j++) acc[j] = make_float4(0.f, 0.f, 0.f, 0.f);

#pragma unroll 4
    for (int k4 = 0; k4 < 16; k4++) {
        float4 wv0 = *(const float4*)&sW[(k4 * 4 + 0) * D + c];
        float4 wv1 = *(const float4*)&sW[(k4 * 4 + 1) * D + c];
        float4 wv2 = *(const float4*)&sW[(k4 * 4 + 2) * D + c];
        float4 wv3 = *(const float4*)&sW[(k4 * 4 + 3) * D + c];
#pragma unroll
        for (int j = 0; j < 8; j++) {
            float4 xv = *(const float4*)&sX[(wr + rg + 4 * j) * RP2 + k4 * 4];
            acc[j].x += xv.x * wv0.x + xv.y * wv1.x + xv.z * wv2.x + xv.w * wv3.x;
            acc[j].y += xv.x * wv0.y + xv.y * wv1.y + xv.z * wv2.y + xv.w * wv3.y;
            acc[j].z += xv.x * wv0.z + xv.y * wv1.z + xv.z * wv2.z + xv.w * wv3.z;
            acc[j].w += xv.x * wv0.w + xv.y * wv1.w + xv.z * wv2.w + xv.w * wv3.w;
        }
    }

#pragma unroll
    for (int j = 0; j < 8; j++) {
        int n = n0 + wr + rg + 4 * j;
        if (n < NN) {
            float s = g_dinv[n];
            __nv_bfloat162 p0 = __floats2bfloat162_rn(s * acc[j].x, s * acc[j].y);
            __nv_bfloat162 p1 = __floats2bfloat162_rn(s * acc[j].z, s * acc[j].w);
            *(__nv_bfloat162*)&g_ybf[n * 32 + (c >> 1)]     = p0;
            *(__nv_bfloat162*)&g_ybf[n * 32 + (c >> 1) + 1] = p1;
        }
    }
}

__global__ void __launch_bounds__(256) k_gemm1(const float* __restrict__ X,
                                               const float* __restrict__ W) {
    gemm_body(X, W, blockIdx.x * 128);
}
__global__ void __launch_bounds__(256) k_gemm2(const float* __restrict__ W) {
    gemm_body(g_h, W, blockIdx.x * 128);
}

// ---------------- fused gather + finalize (bf16 messages) ----------------
// 16 threads per node; each handles 4 features = 2 bf162 = one uint2 (8B).
__device__ __forceinline__ void gather_body(const float* __restrict__ b,
                                            const int* __restrict__ batch,
                                            float* __restrict__ pool,
                                            int store_h) {
    int idx = blockIdx.x * blockDim.x + threadIdx.x;
    int n = idx >> 4;
    int q = idx & 15;
    if (n >= NN) return;
    const uint2* y2 = (const uint2*)g_ybf;     // 16 x uint2 per row

    uint2 raw = y2[n * 16 + q];                // self loop term
    __nv_bfloat162 b0 = *(__nv_bfloat162*)&raw.x;
    __nv_bfloat162 b1 = *(__nv_bfloat162*)&raw.y;
    float2 f0 = __bfloat1622float2(b0);
    float2 f1 = __bfloat1622float2(b1);
    float4 acc = make_float4(f0.x, f0.y, f1.x, f1.y);

    int s = g_start[n], e = g_start[n + 1];
    for (int ei = s; ei < e; ei++) {
        unsigned c = (unsigned)g_ecol[ei];
        if (c < NN) {
            uint2 rv = y2[c * 16 + q];
            __nv_bfloat162 v0 = *(__nv_bfloat162*)&rv.x;
            __nv_bfloat162 v1 = *(__nv_bfloat162*)&rv.y;
            float2 g0 = __bfloat1622float2(v0);
            float2 g1 = __bfloat1622float2(v1);
            acc.x += g0.x; acc.y += g0.y; acc.z += g1.x; acc.w += g1.y;
        }
    }
    float sc = g_dinv[n];
    float4 bb = ((const float4*)b)[q];
    float4 h;
    h.x = fmaxf(sc * acc.x + bb.x, 0.0f);
    h.y = fmaxf(sc * acc.y + bb.y, 0.0f);
    h.z = fmaxf(sc * acc.z + bb.z, 0.0f);
    h.w = fmaxf(sc * acc.w + bb.w, 0.0f);
    if (store_h) ((float4*)g_h)[n * 16 + q] = h;
    unsigned g = (unsigned)batch[n];
    if (g < NG) red_v4(((float4*)pool) + g * 16 + q, h);
}

__global__ void k_gather1(const float* __restrict__ b, const int* __restrict__ batch) {
    gather_body(b, batch, g_pool1, 1);
}
__global__ void k_gather2(const float* __restrict__ b, const int* __restrict__ batch) {
    gather_body(b, batch, g_pool2, 0);
}

// ---------------- head ----------------
__global__ void k_head(const float* __restrict__ Wl, const float* __restrict__ bl,
                       float* __restrict__ out) {
    int g = blockIdx.x;
    int lane = threadIdx.x;  // 32
    float denom = fmaxf((float)g_cnti[g], 1.0f);
    float v0 = (g_pool1[g * D + lane] + g_pool2[g * D + lane]) / denom;
    float v1 = (g_pool1[g * D + 32 + lane] + g_pool2[g * D + 32 + lane]) / denom;
    float z = (lane < NC) ? bl[lane] : 0.0f;
#pragma unroll
    for (int d = 0; d < 32; d++) {
        float a0 = __shfl_sync(0xffffffffu, v0, d);
        float a1 = __shfl_sync(0xffffffffu, v1, d);
        if (lane < NC) z += a0 * Wl[d * NC + lane] + a1 * Wl[(d + 32) * NC + lane];
    }
    if (lane < NC) z = fmaxf(z, 0.0f);
    float zm = (lane < NC) ? z : -1e30f;
#pragma unroll
    for (int off = 16; off; off >>= 1)
        zm = fmaxf(zm, __shfl_xor_sync(0xffffffffu, zm, off));
    float e = (lane < NC) ? expf(z - zm) : 0.0f;
#pragma unroll
    for (int off = 16; off; off >>= 1)
        e += __shfl_xor_sync(0xffffffffu, e, off);
    if (lane < NC) out[g * NC + lane] = z - zm - logf(e);
}

// ---------------- launch ----------------

extern "C" void kernel_launch(void* const* d_in, const int* in_sizes, int n_in,
                              void* d_out, int out_size) {
    const float* x     = (const float*)d_in[0];
    const int*   eidx  = (const int*)d_in[1];    // int32 (JAX x64 disabled)
    const int*   batch = (const int*)d_in[2];
    const float* W1    = (const float*)d_in[3];
    const float* b1    = (const float*)d_in[4];
    const float* W2    = (const float*)d_in[5];
    const float* b2    = (const float*)d_in[6];
    const float* Wl    = (const float*)d_in[7];
    const float* bl    = (const float*)d_in[8];
    float* out = (float*)d_out;

    const int* rows = eidx;        // edge_index[0] = targets
    const int* cols = eidx + NE;   // edge_index[1] = sources

    const int GB = (NN + 127) / 128;

    k_init<<<(NN + 255) / 256, 256>>>();
    k_deg<<<(NE + 255) / 256, 256>>>(rows);

    // CSR build + dinv + counts (scanA fuses prep)
    k_scanA<<<NB, 256>>>(batch);
    k_scanB<<<1, 512>>>();
    k_scanC<<<NB, 256>>>();
    k_fill<<<(NE + 255) / 256, 256>>>(rows, cols);

    // conv1
    k_gemm1<<<GB, 256>>>(x, W1);
    k_gather1<<<(NN * 16 + 255) / 256, 256>>>(b1, batch);

    // conv2
    k_gemm2<<<GB, 256>>>(W2);
    k_gather2<<<(NN * 16 + 255) / 256, 256>>>(b2, batch);

    // head
    k_head<<<NG, 32>>>(Wl, bl, out);
}

// round 11
// speedup vs baseline: 1.3437x; 1.2531x over previous
#include <cuda_runtime.h>
#include <cuda_bf16.h>

#define NN 100000
#define NE 1200000
#define NG 512
#define D  64
#define NC 10
#define NB 391            // scan blocks = ceil(NN/256)
#define NCHUNK 6250       // NN/16 exactly
#define GEMM_BLOCKS 250
#define GEMM_WARPS (GEMM_BLOCKS * 8)
#define RPX 72            // bf16 smem row pad (144B): conflict-free frag loads
#define RPW 72

// ---------------- scratch (device globals; no allocation) ----------------
__device__ int   g_degi[NN];
__device__ float g_dinv[NN];
__device__ __nv_bfloat162 g_ybf[NN * 32];   // y rows bf16 (32 bf162 = 64 vals)
__device__ __nv_bfloat16  g_hbf[NN * D];    // layer-1 activations bf16
__device__ float g_pool1[NG * D];
__device__ float g_pool2[NG * D];
__device__ int   g_cnti[NG];
// CSR
__device__ int   g_scan[NN];
__device__ int   g_bsum[NB];
__device__ int   g_boff[NB];
__device__ int   g_start[NN + 1];
__device__ int   g_pos[NN];
__device__ int   g_ecol[NE];

__device__ __forceinline__ void red_v4(float4* dst, float4 v) {
    asm volatile("red.global.add.v4.f32 [%0], {%1,%2,%3,%4};"
                 :: "l"(dst), "f"(v.x), "f"(v.y), "f"(v.z), "f"(v.w) : "memory");
}

__device__ __forceinline__ void mma16(float d[4], const unsigned a[4],
                                      const unsigned b[2]) {
    asm volatile(
        "mma.sync.aligned.m16n8k16.row.col.f32.bf16.bf16.f32 "
        "{%0,%1,%2,%3}, {%4,%5,%6,%7}, {%8,%9}, {%0,%1,%2,%3};"
        : "+f"(d[0]), "+f"(d[1]), "+f"(d[2]), "+f"(d[3])
        : "r"(a[0]), "r"(a[1]), "r"(a[2]), "r"(a[3]), "r"(b[0]), "r"(b[1]));
}

// ---------------- setup kernels ----------------

__global__ void k_init() {
    int i = blockIdx.x * blockDim.x + threadIdx.x;
    if (i < NN) g_degi[i] = 0;
    if (i < NG * D) { g_pool1[i] = 0.0f; g_pool2[i] = 0.0f; }
    if (i < NG) g_cnti[i] = 0;
}

__global__ void k_deg(const int* __restrict__ rows) {
    int e = blockIdx.x * blockDim.x + threadIdx.x;
    if (e >= NE) return;
    unsigned r = (unsigned)rows[e];
    if (r < NN) atomicAdd(&g_degi[r], 1);
}

// per-block inclusive scan of degrees; fused: dinv + per-graph counts
__global__ void k_scanA(const int* __restrict__ batch) {
    __shared__ int s[256];
    int t = threadIdx.x;
    int i = blockIdx.x * 256 + t;
    int d = (i < NN) ? g_degi[i] : 0;
    s[t] = d;
    if (i < NN) {
        g_dinv[i] = rsqrtf((float)d + 1.0f);   // +1 = self loop
        unsigned g = (unsigned)batch[i];
        if (g < NG) atomicAdd(&g_cnti[g], 1);
    }
    __syncthreads();
#pragma unroll
    for (int off = 1; off < 256; off <<= 1) {
        int v = (t >= off) ? s[t - off] : 0;
        __syncthreads();
        s[t] += v;
        __syncthreads();
    }
    if (i < NN) g_scan[i] = s[t];
    if (t == 255) g_bsum[blockIdx.x] = s[255];
}

// single-block exclusive scan of block sums (shuffle-based)
__global__ void k_scanB() {
    __shared__ int wsum[16];
    int t = threadIdx.x;  // 512
    int lane = t & 31, w = t >> 5;
    int v = (t < NB) ? g_bsum[t] : 0;
    int s = v;
#pragma unroll
    for (int off = 1; off < 32; off <<= 1) {
        int u = __shfl_up_sync(0xffffffffu, s, off);
        if (lane >= off) s += u;
    }
    if (lane == 31) wsum[w] = s;
    __syncthreads();
    if (w == 0) {
        int ws = (lane < 16) ? wsum[lane] : 0;
#pragma unroll
        for (int off = 1; off < 16; off <<= 1) {
            int u = __shfl_up_sync(0xffffffffu, ws, off);
            if (lane >= off) ws += u;
        }
        if (lane < 16) wsum[lane] = ws;
        if (lane == 15) g_start[NN] = ws;
    }
    __syncthreads();
    int base = (w > 0) ? wsum[w - 1] : 0;
    if (t < NB) g_boff[t] = base + s - v;
}

__global__ void k_scanC() {
    int i = blockIdx.x * blockDim.x + threadIdx.x;
    if (i >= NN) return;
    int st = g_scan[i] - g_degi[i] + g_boff[i >> 8];
    g_start[i] = st;
    g_pos[i] = st;
}

__global__ void k_fill(const int* __restrict__ rows, const int* __restrict__ cols) {
    int e = blockIdx.x * blockDim.x + threadIdx.x;
    if (e >= NE) return;
    unsigned r = (unsigned)rows[e];
    if (r >= NN) return;
    int p = atomicAdd(&g_pos[r], 1);
    g_ecol[p] = cols[e];
}

// ---------------- tensor-core GEMM: g_ybf = bf16(dinv * (X W)) ----------------
// 8 warps/block; warp owns 16-row chunks (grid-stride). B frags (all of W,
// transposed bf16 smem) built once per warp; A staged warp-privately.

// stage W (fp32, row-major [k][n]) -> sWt[n][k] bf16
__device__ __forceinline__ void stage_Wt(__nv_bfloat16* sWt,
                                         const float* __restrict__ W) {
    int t = threadIdx.x;
    for (int i = t; i < 4096; i += 256) {
        int k = i >> 6, n = i & 63;
        sWt[n * RPW + k] = __float2bfloat16(W[i]);
    }
    __syncthreads();
}

__device__ __forceinline__ void build_B(unsigned bfr[8][4][2],
                                        const __nv_bfloat16* sWt, int lane) {
#pragma unroll
    for (int nt = 0; nt < 8; nt++) {
        int n = nt * 8 + (lane >> 2);
#pragma unroll
        for (int ks = 0; ks < 4; ks++) {
            bfr[nt][ks][0] = *(const unsigned*)&sWt[n * RPW + ks * 16 + (lane & 3) * 2];
            bfr[nt][ks][1] = *(const unsigned*)&sWt[n * RPW + ks * 16 + 8 + (lane & 3) * 2];
        }
    }
}

__device__ __forceinline__ void mma_chunk(const __nv_bfloat16* myX,
                                          const unsigned bfr[8][4][2],
                                          int lane, int n0) {
    float dreg[8][4];
#pragma unroll
    for (int nt = 0; nt < 8; nt++)
#pragma unroll
        for (int j = 0; j < 4; j++) dreg[nt][j] = 0.0f;

#pragma unroll
    for (int ks = 0; ks < 4; ks++) {
        unsigned a[4];
        a[0] = *(const unsigned*)&myX[(lane >> 2) * RPX + ks * 16 + (lane & 3) * 2];
        a[1] = *(const unsigned*)&myX[((lane >> 2) + 8) * RPX + ks * 16 + (lane & 3) * 2];
        a[2] = *(const unsigned*)&myX[(lane >> 2) * RPX + ks * 16 + 8 + (lane & 3) * 2];
        a[3] = *(const unsigned*)&myX[((lane >> 2) + 8) * RPX + ks * 16 + 8 + (lane & 3) * 2];
#pragma unroll
        for (int nt = 0; nt < 8; nt++) mma16(dreg[nt], a, bfr[nt][ks]);
    }

    int r0 = n0 + (lane >> 2), r1 = r0 + 8;
    float s0 = g_dinv[r0];
    float s1 = g_dinv[r1];
#pragma unroll
    for (int nt = 0; nt < 8; nt++) {
        g_ybf[r0 * 32 + nt * 4 + (lane & 3)] =
            __floats2bfloat162_rn(s0 * dreg[nt][0], s0 * dreg[nt][1]);
        g_ybf[r1 * 32 + nt * 4 + (lane & 3)] =
            __floats2bfloat162_rn(s1 * dreg[nt][2], s1 * dreg[nt][3]);
    }
}

__global__ void __launch_bounds__(256) k_gemm1(const float* __restrict__ X,
                                               const float* __restrict__ W) {
    __shared__ __nv_bfloat16 sWt[64 * RPW];
    __shared__ __nv_bfloat16 sX[8][16 * RPX];
    int t = threadIdx.x, lane = t & 31, w = t >> 5;
    stage_Wt(sWt, W);
    unsigned bfr[8][4][2];
    build_B(bfr, sWt, lane);
    __nv_bfloat16* myX = sX[w];
    for (int ch = blockIdx.x * 8 + w; ch < NCHUNK; ch += GEMM_WARPS) {
        int n0 = ch * 16;
        // stage 16 rows fp32 -> bf16 (warp-private)
#pragma unroll
        for (int i = 0; i < 8; i++) {
            int idx = lane + 32 * i;           // 0..255
            int r = idx >> 4, c4 = idx & 15;
            float4 v = ((const float4*)X)[(n0 + r) * 16 + c4];
            *(__nv_bfloat162*)&myX[r * RPX + c4 * 4] = __floats2bfloat162_rn(v.x, v.y);
            *(__nv_bfloat162*)&myX[r * RPX + c4 * 4 + 2] = __floats2bfloat162_rn(v.z, v.w);
        }
        __syncwarp();
        mma_chunk(myX, bfr, lane, n0);
        __syncwarp();
    }
}

__global__ void __launch_bounds__(256) k_gemm2(const float* __restrict__ W) {
    __shared__ __nv_bfloat16 sWt[64 * RPW];
    __shared__ __nv_bfloat16 sX[8][16 * RPX];
    int t = threadIdx.x, lane = t & 31, w = t >> 5;
    stage_Wt(sWt, W);
    unsigned bfr[8][4][2];
    build_B(bfr, sWt, lane);
    __nv_bfloat16* myX = sX[w];
    for (int ch = blockIdx.x * 8 + w; ch < NCHUNK; ch += GEMM_WARPS) {
        int n0 = ch * 16;
        // stage 16 bf16 rows (warp-private), no conversion
#pragma unroll
        for (int i = 0; i < 4; i++) {
            int idx = lane + 32 * i;           // 0..127
            int r = idx >> 3, c8 = idx & 7;
            uint4 v = ((const uint4*)g_hbf)[(n0 + r) * 8 + c8];
            *(uint4*)&myX[r * RPX + c8 * 8] = v;
        }
        __syncwarp();
        mma_chunk(myX, bfr, lane, n0);
        __syncwarp();
    }
}

// ---------------- fused gather + finalize (bf16 messages) ----------------
__device__ __forceinline__ void gather_body(const float* __restrict__ b,
                                            const int* __restrict__ batch,
                                            float* __restrict__ pool,
                                            int store_h) {
    int idx = blockIdx.x * blockDim.x + threadIdx.x;
    int n = idx >> 4;
    int q = idx & 15;
    if (n >= NN) return;
    const uint2* y2 = (const uint2*)g_ybf;     // 16 x uint2 per row

    uint2 raw = y2[n * 16 + q];                // self loop term
    float2 f0 = __bfloat1622float2(*(__nv_bfloat162*)&raw.x);
    float2 f1 = __bfloat1622float2(*(__nv_bfloat162*)&raw.y);
    float4 acc = make_float4(f0.x, f0.y, f1.x, f1.y);

    int s = g_start[n], e = g_start[n + 1];
    for (int ei = s; ei < e; ei++) {
        unsigned c = (unsigned)g_ecol[ei];
        if (c < NN) {
            uint2 rv = y2[c * 16 + q];
            float2 g0 = __bfloat1622float2(*(__nv_bfloat162*)&rv.x);
            float2 g1 = __bfloat1622float2(*(__nv_bfloat162*)&rv.y);
            acc.x += g0.x; acc.y += g0.y; acc.z += g1.x; acc.w += g1.y;
        }
    }
    float sc = g_dinv[n];
    float4 bb = ((const float4*)b)[q];
    float4 h;
    h.x = fmaxf(sc * acc.x + bb.x, 0.0f);
    h.y = fmaxf(sc * acc.y + bb.y, 0.0f);
    h.z = fmaxf(sc * acc.z + bb.z, 0.0f);
    h.w = fmaxf(sc * acc.w + bb.w, 0.0f);
    if (store_h) {
        uint2 pk;
        __nv_bfloat162 p0 = __floats2bfloat162_rn(h.x, h.y);
        __nv_bfloat162 p1 = __floats2bfloat162_rn(h.z, h.w);
        pk.x = *(unsigned*)&p0; pk.y = *(unsigned*)&p1;
        *(uint2*)&g_hbf[n * 64 + q * 4] = pk;
    }
    unsigned g = (unsigned)batch[n];
    if (g < NG) red_v4(((float4*)pool) + g * 16 + q, h);
}

__global__ void k_gather1(const float* __restrict__ b, const int* __restrict__ batch) {
    gather_body(b, batch, g_pool1, 1);
}
__global__ void k_gather2(const float* __restrict__ b, const int* __restrict__ batch) {
    gather_body(b, batch, g_pool2, 0);
}

// ---------------- head ----------------
__global__ void k_head(const float* __restrict__ Wl, const float* __restrict__ bl,
                       float* __restrict__ out) {
    int g = blockIdx.x;
    int lane = threadIdx.x;  // 32
    float denom = fmaxf((float)g_cnti[g], 1.0f);
    float v0 = (g_pool1[g * D + lane] + g_pool2[g * D + lane]) / denom;
    float v1 = (g_pool1[g * D + 32 + lane] + g_pool2[g * D + 32 + lane]) / denom;
    float z = (lane < NC) ? bl[lane] : 0.0f;
#pragma unroll
    for (int d = 0; d < 32; d++) {
        float a0 = __shfl_sync(0xffffffffu, v0, d);
        float a1 = __shfl_sync(0xffffffffu, v1, d);
        if (lane < NC) z += a0 * Wl[d * NC + lane] + a1 * Wl[(d + 32) * NC + lane];
    }
    if (lane < NC) z = fmaxf(z, 0.0f);
    float zm = (lane < NC) ? z : -1e30f;
#pragma unroll
    for (int off = 16; off; off >>= 1)
        zm = fmaxf(zm, __shfl_xor_sync(0xffffffffu, zm, off));
    float e = (lane < NC) ? expf(z - zm) : 0.0f;
#pragma unroll
    for (int off = 16; off; off >>= 1)
        e += __shfl_xor_sync(0xffffffffu, e, off);
    if (lane < NC) out[g * NC + lane] = z - zm - logf(e);
}

// ---------------- launch ----------------

extern "C" void kernel_launch(void* const* d_in, const int* in_sizes, int n_in,
                              void* d_out, int out_size) {
    const float* x     = (const float*)d_in[0];
    const int*   eidx  = (const int*)d_in[1];    // int32 (JAX x64 disabled)
    const int*   batch = (const int*)d_in[2];
    const float* W1    = (const float*)d_in[3];
    const float* b1    = (const float*)d_in[4];
    const float* W2    = (const float*)d_in[5];
    const float* b2    = (const float*)d_in[6];
    const float* Wl    = (const float*)d_in[7];
    const float* bl    = (const float*)d_in[8];
    float* out = (float*)d_out;

    const int* rows = eidx;        // edge_index[0] = targets
    const int* cols = eidx + NE;   // edge_index[1] = sources

    k_init<<<(NN + 255) / 256, 256>>>();
    k_deg<<<(NE + 255) / 256, 256>>>(rows);

    // CSR build + dinv + counts
    k_scanA<<<NB, 256>>>(batch);
    k_scanB<<<1, 512>>>();
    k_scanC<<<NB, 256>>>();
    k_fill<<<(NE + 255) / 256, 256>>>(rows, cols);

    // conv1
    k_gemm1<<<GEMM_BLOCKS, 256>>>(x, W1);
    k_gather1<<<(NN * 16 + 255) / 256, 256>>>(b1, batch);

    // conv2
    k_gemm2<<<GEMM_BLOCKS, 256>>>(W2);
    k_gather2<<<(NN * 16 + 255) / 256, 256>>>(b2, batch);

    // head
    k_head<<<NG, 32>>>(Wl, bl, out);
}